// round 6
// baseline (speedup 1.0000x reference)
#include <cuda_runtime.h>

// Inverse db4 wavelet reconstruction (polyphase, hardcoded taps, persistent grid).
// in : [B=16, L=16000, 128]  (first 64 ch = approx, last 64 = detail)
// out: [B=16, 2L=32000, 64]
//
//   out[2k]   = l1*a[k-1]+l3*a[k]+l5*a[k+1]+l7*a[k+2] + h1*d[...]...
//   out[2k+1] = l0*a[k-1]+l2*a[k]+l4*a[k+1]+l6*a[k+2] + h0*d[...]...
// x out of [0,L) is zero.

#define BATCH 16
#define SEQ_L 16000
#define C_IN  128
#define C_OUT 64
#define KPT   4          // k positions per thread
#define NW    (KPT + 3)  // rows in the load window (7)
#define TPB   128        // 16 c4-groups x 8 k-tiles per block

#define SMS            148
#define BLOCKS_PER_SM  8
#define GRID           (SMS * BLOCKS_PER_SM)   // 1184: one wave

// db4 dec_lo
#define D0 (-0.010597401784997278f)
#define D1 ( 0.032883011666982945f)
#define D2 ( 0.030841381835986965f)
#define D3 (-0.18703481171888114f)
#define D4 (-0.02798376941698385f)
#define D5 ( 0.6308807679295904f)
#define D6 ( 0.7148465705525415f)
#define D7 ( 0.23037781330885523f)
// rec_lo[i] = dec_lo[7-i]
#define L0 D7
#define L1 D6
#define L2 D5
#define L3 D4
#define L4 D3
#define L5 D2
#define L6 D1
#define L7 D0
// rec_hi[i] = (-1)^i * dec_lo[i]
#define H0 ( D0)
#define H1 (-D1)
#define H2 ( D2)
#define H3 (-D3)
#define H4 ( D4)
#define H5 (-D5)
#define H6 ( D6)
#define H7 (-D7)

__device__ __forceinline__ float4 f4zero() { return make_float4(0.f, 0.f, 0.f, 0.f); }

__device__ __forceinline__ void f4fma(float s, const float4& a, float4& acc) {
    acc.x = fmaf(a.x, s, acc.x);
    acc.y = fmaf(a.y, s, acc.y);
    acc.z = fmaf(a.z, s, acc.z);
    acc.w = fmaf(a.w, s, acc.w);
}

__global__ __launch_bounds__(TPB, BLOCKS_PER_SM)
void idwt_db4_kernel(const float* __restrict__ in,
                     float* __restrict__ out)
{
    const int tid = threadIdx.x;
    const int c4  = tid & 15;          // channel group of 4 (0..15)
    const int lk  = tid >> 4;          // local k-tile (0..7)

    constexpr int KTILES_PER_BLOCK = TPB / 16;                          // 8
    constexpr int K_PER_TILE       = KPT * KTILES_PER_BLOCK;            // 32
    constexpr int TILES_PER_BATCH  = SEQ_L / K_PER_TILE;                // 500
    constexpr int NUM_TILES        = BATCH * TILES_PER_BATCH;           // 8000

    // Multiply-free batch decomposition, updated across the grid-stride loop.
    int b   = blockIdx.x / TILES_PER_BATCH;
    int blk = blockIdx.x - b * TILES_PER_BATCH;

    for (int t = blockIdx.x; t < NUM_TILES; t += GRID) {
        const int k0  = blk * K_PER_TILE + lk * KPT;

        const float* ap = in + (size_t)b * SEQ_L * C_IN + c4 * 4;   // approx base
        float* op = out + (size_t)b * (2 * SEQ_L) * C_OUT + c4 * 4;

        float4 a[NW], d[NW];

        if (k0 >= 1 && k0 + KPT + 2 <= SEQ_L) {
            // Interior: unpredicated, front-batched loads.
            const float* p = ap + (size_t)(k0 - 1) * C_IN;
#pragma unroll
            for (int i = 0; i < NW; ++i) {
                a[i] = *reinterpret_cast<const float4*>(p + (size_t)i * C_IN);
                d[i] = *reinterpret_cast<const float4*>(p + (size_t)i * C_IN + C_OUT);
            }
        } else {
            // Batch edge: predicated loads with zero fill.
#pragma unroll
            for (int i = 0; i < NW; ++i) {
                const int k = k0 - 1 + i;
                if ((unsigned)k < (unsigned)SEQ_L) {
                    const float* p = ap + (size_t)k * C_IN;
                    a[i] = *reinterpret_cast<const float4*>(p);
                    d[i] = *reinterpret_cast<const float4*>(p + C_OUT);
                } else {
                    a[i] = f4zero();
                    d[i] = f4zero();
                }
            }
        }

#pragma unroll
        for (int i = 0; i < KPT; ++i) {
            const int k = k0 + i;

            float4 ev = f4zero();   // out[2k]
            f4fma(L1, a[i], ev); f4fma(L3, a[i + 1], ev); f4fma(L5, a[i + 2], ev); f4fma(L7, a[i + 3], ev);
            f4fma(H1, d[i], ev); f4fma(H3, d[i + 1], ev); f4fma(H5, d[i + 2], ev); f4fma(H7, d[i + 3], ev);

            float4 od = f4zero();   // out[2k+1]
            f4fma(L0, a[i], od); f4fma(L2, a[i + 1], od); f4fma(L4, a[i + 2], od); f4fma(L6, a[i + 3], od);
            f4fma(H0, d[i], od); f4fma(H2, d[i + 1], od); f4fma(H4, d[i + 2], od); f4fma(H6, d[i + 3], od);

            __stcs(reinterpret_cast<float4*>(op + (size_t)(2 * k) * C_OUT), ev);
            __stcs(reinterpret_cast<float4*>(op + (size_t)(2 * k + 1) * C_OUT), od);
        }

        // advance (t += GRID) => (b, blk) update without div/mod
        blk += GRID;
        while (blk >= TILES_PER_BATCH) { blk -= TILES_PER_BATCH; ++b; }
    }
}

extern "C" void kernel_launch(void* const* d_in, const int* in_sizes, int n_in,
                              void* d_out, int out_size)
{
    const float* in = (const float*)d_in[0];
    float* out      = (float*)d_out;
    (void)in_sizes; (void)n_in; (void)out_size;

    idwt_db4_kernel<<<GRID, TPB>>>(in, out);
}

// round 7
// speedup vs baseline: 1.1058x; 1.1058x over previous
#include <cuda_runtime.h>

// Inverse db4 wavelet reconstruction (polyphase form, hardcoded db4 taps).
// in : [B=16, L=16000, 128]  (first 64 ch = approx, last 64 = detail)
// out: [B=16, 2L=32000, 64]
//
//   out[2k]   = l1*a[k-1]+l3*a[k]+l5*a[k+1]+l7*a[k+2] + h1*d[k-1]+h3*d[k]+h5*d[k+1]+h7*d[k+2]
//   out[2k+1] = l0*a[k-1]+l2*a[k]+l4*a[k+1]+l6*a[k+2] + h0*d[k-1]+h2*d[k]+h4*d[k+1]+h6*d[k+2]
// x out of [0,L) is zero.
//
// Traffic is compulsory: 131 MB read + 131 MB write. Kernel runs at the mixed
// R/W HBM floor; loads are evict-first (__ldcs) and stores streaming (__stcs)
// to keep L2 available for the short-reuse overlap window.

#define BATCH 16
#define SEQ_L 16000
#define C_IN  128
#define C_OUT 64
#define KPT   4          // k positions per thread
#define NW    (KPT + 3)  // rows in the load window (7)
#define TPB   128        // 16 c4-groups x 8 k-tiles per block

// db4 dec_lo
#define D0 (-0.010597401784997278f)
#define D1 ( 0.032883011666982945f)
#define D2 ( 0.030841381835986965f)
#define D3 (-0.18703481171888114f)
#define D4 (-0.02798376941698385f)
#define D5 ( 0.6308807679295904f)
#define D6 ( 0.7148465705525415f)
#define D7 ( 0.23037781330885523f)
// rec_lo[i] = dec_lo[7-i]
#define L0 D7
#define L1 D6
#define L2 D5
#define L3 D4
#define L4 D3
#define L5 D2
#define L6 D1
#define L7 D0
// rec_hi[i] = (-1)^i * dec_lo[i]
#define H0 ( D0)
#define H1 (-D1)
#define H2 ( D2)
#define H3 (-D3)
#define H4 ( D4)
#define H5 (-D5)
#define H6 ( D6)
#define H7 (-D7)

__device__ __forceinline__ float4 f4zero() { return make_float4(0.f, 0.f, 0.f, 0.f); }

__device__ __forceinline__ void f4fma(float s, const float4& a, float4& acc) {
    acc.x = fmaf(a.x, s, acc.x);
    acc.y = fmaf(a.y, s, acc.y);
    acc.z = fmaf(a.z, s, acc.z);
    acc.w = fmaf(a.w, s, acc.w);
}

__global__ __launch_bounds__(TPB)
void idwt_db4_kernel(const float* __restrict__ in,
                     float* __restrict__ out)
{
    const int tid = threadIdx.x;
    const int c4  = tid & 15;          // channel group of 4 (0..15)
    const int lk  = tid >> 4;          // local k-tile (0..7)

    constexpr int KTILES_PER_BLOCK = TPB / 16;                          // 8
    constexpr int BLOCKS_PER_BATCH = SEQ_L / (KPT * KTILES_PER_BLOCK);  // 500

    const int b   = blockIdx.x / BLOCKS_PER_BATCH;
    const int blk = blockIdx.x % BLOCKS_PER_BATCH;
    const int k0  = (blk * KTILES_PER_BLOCK + lk) * KPT;

    const float* ap = in + (size_t)b * SEQ_L * C_IN + c4 * 4;   // approx base
    float* op = out + (size_t)b * (2 * SEQ_L) * C_OUT + c4 * 4;

    float4 a[NW], d[NW];

    if (k0 >= 1 && k0 + KPT + 2 <= SEQ_L) {
        // Interior: unpredicated, front-batched streaming loads.
        const float* p = ap + (size_t)(k0 - 1) * C_IN;
#pragma unroll
        for (int i = 0; i < NW; ++i) {
            a[i] = __ldcs(reinterpret_cast<const float4*>(p + (size_t)i * C_IN));
            d[i] = __ldcs(reinterpret_cast<const float4*>(p + (size_t)i * C_IN + C_OUT));
        }
    } else {
        // Batch edge: predicated loads with zero fill.
#pragma unroll
        for (int i = 0; i < NW; ++i) {
            const int k = k0 - 1 + i;
            if ((unsigned)k < (unsigned)SEQ_L) {
                const float* p = ap + (size_t)k * C_IN;
                a[i] = __ldcs(reinterpret_cast<const float4*>(p));
                d[i] = __ldcs(reinterpret_cast<const float4*>(p + C_OUT));
            } else {
                a[i] = f4zero();
                d[i] = f4zero();
            }
        }
    }

#pragma unroll
    for (int i = 0; i < KPT; ++i) {
        const int k = k0 + i;

        float4 ev = f4zero();   // out[2k]
        f4fma(L1, a[i], ev); f4fma(L3, a[i + 1], ev); f4fma(L5, a[i + 2], ev); f4fma(L7, a[i + 3], ev);
        f4fma(H1, d[i], ev); f4fma(H3, d[i + 1], ev); f4fma(H5, d[i + 2], ev); f4fma(H7, d[i + 3], ev);

        float4 od = f4zero();   // out[2k+1]
        f4fma(L0, a[i], od); f4fma(L2, a[i + 1], od); f4fma(L4, a[i + 2], od); f4fma(L6, a[i + 3], od);
        f4fma(H0, d[i], od); f4fma(H2, d[i + 1], od); f4fma(H4, d[i + 2], od); f4fma(H6, d[i + 3], od);

        __stcs(reinterpret_cast<float4*>(op + (size_t)(2 * k) * C_OUT), ev);
        __stcs(reinterpret_cast<float4*>(op + (size_t)(2 * k + 1) * C_OUT), od);
    }
}

extern "C" void kernel_launch(void* const* d_in, const int* in_sizes, int n_in,
                              void* d_out, int out_size)
{
    const float* in = (const float*)d_in[0];
    float* out      = (float*)d_out;
    (void)in_sizes; (void)n_in; (void)out_size;

    constexpr int KTILES_PER_BLOCK = TPB / 16;                          // 8
    constexpr int BLOCKS_PER_BATCH = SEQ_L / (KPT * KTILES_PER_BLOCK);  // 500
    const dim3 grid(BATCH * BLOCKS_PER_BATCH);                          // 8000 blocks

    idwt_db4_kernel<<<grid, TPB>>>(in, out);
}